// round 6
// baseline (speedup 1.0000x reference)
#include <cuda_runtime.h>
#include <cuda_bf16.h>

#define NF   256     // feature dim
#define DEG  32      // neighbors per node
#define MM   33      // subgraph size (target + neighbors)
#define BMAX 10240   // max batch (actual B=10000)

// Scratch (allocation-free: __device__ globals)
__device__ __align__(16) float g_mix[(size_t)BMAX * NF];
__device__ float g_c0[BMAX];

__device__ __forceinline__ void cp_async16(void* smem_dst, const void* gmem_src) {
    unsigned saddr = (unsigned)__cvta_generic_to_shared(smem_dst);
    asm volatile("cp.async.ca.shared.global [%0], [%1], 16;\n"
                 :: "r"(saddr), "l"(gmem_src) : "memory");
}
__device__ __forceinline__ void cp_async_commit() {
    asm volatile("cp.async.commit_group;\n" ::: "memory");
}
template <int N>
__device__ __forceinline__ void cp_async_wait() {
    asm volatile("cp.async.wait_group %0;\n" :: "n"(N) : "memory");
}

// ---------------------------------------------------------------------------
// Kernel A: per-target subgraph construction + weighted feature mix.
// cp.async prefetches the 33x256 feature tile while bitmask phases compute.
// ---------------------------------------------------------------------------
__global__ void __launch_bounds__(256) subgraph_kernel(
    const float* __restrict__ feat,   // [N_NODES, NF]
    const int*   __restrict__ adj,    // [N_NODES, DEG]
    const int*   __restrict__ bn,     // [B]
    int B)
{
    __shared__ int   s_ids[MM];
    __shared__ __align__(16) int s_adj[MM][DEG];
    __shared__ __align__(16) float4 s_feat[MM][NF / 4];   // 33 KB feature stage
    __shared__ unsigned long long s_row[MM];
    __shared__ int   s_valid[MM];
    __shared__ float s_c[MM];
    __shared__ float s_w[MM];
    __shared__ __align__(16) float4 s_acc[4][NF / 4];

    const int b = blockIdx.x;
    const int t = threadIdx.x;

    // ---- phase 1: subgraph node ids s = [v, adj[v]] ----
    const int v = bn[b];
    if (t == 0)  s_ids[0] = v;
    if (t < DEG) s_ids[1 + t] = adj[(size_t)v * DEG + t];
    __syncthreads();

    // ---- async group 0: adjacency rows (33 x 8 int4) ----
    for (int idx = t; idx < MM * (DEG / 4); idx += 256) {
        int i = idx >> 3, q = idx & 7;
        cp_async16(&s_adj[i][q * 4],
                   &adj[(size_t)s_ids[i] * DEG + q * 4]);
    }
    cp_async_commit();

    // ---- async group 1: feature tile (33 x 64 float4) ----
    for (int idx = t; idx < MM * (NF / 4); idx += 256) {
        int i = idx >> 6, c4 = idx & 63;
        cp_async16(&s_feat[i][c4],
                   &feat[(size_t)s_ids[i] * NF + c4 * 4]);
    }
    cp_async_commit();

    // ---- dedup (needs only s_ids) ----
    if (t < MM) {
        int sj = s_ids[t];
        int dup = 0;
        for (int i = 0; i < t; i++) dup |= (s_ids[i] == sj);
        s_valid[t] = !dup;
    }

    cp_async_wait<1>();               // adjacency landed (features may be in flight)
    __syncthreads();

    // ---- phase 3: membership bitmasks; warp w handles rows i = w, w+8, ...
    {
        const int lane = t & 31;
        const int w    = t >> 5;
        const int sj   = s_ids[lane];
        const int s32  = s_ids[32];
        for (int i = w; i < MM; i += 8) {
            const int* arow = s_adj[i];
            bool bit = false, bit32 = false;
            #pragma unroll
            for (int k = 0; k < DEG; k++) {
                int a = arow[k];
                bit   |= (a == sj);
                bit32 |= (a == s32);
            }
            unsigned m = __ballot_sync(0xffffffffu, bit);
            if (lane == 0)
                s_row[i] = (unsigned long long)m |
                           (bit32 ? (1ull << 32) : 0ull);
        }
    }
    __syncthreads();

    // ---- phase 4: validity masking ----
    if (t < MM) {
        unsigned long long vm = 0ull;
        #pragma unroll
        for (int i = 0; i < MM; i++)
            vm |= ((unsigned long long)(s_valid[i] != 0)) << i;
        s_row[t] = s_valid[t] ? (s_row[t] & vm) : 0ull;
    }
    __syncthreads();

    // ---- phase 5: in-degrees -> c ----
    if (t < MM) {
        int cnt = 0;
        #pragma unroll
        for (int i = 0; i < MM; i++)
            cnt += (int)((s_row[i] >> t) & 1ull);
        float deg = (float)(cnt < 1 ? 1 : cnt);
        s_c[t] = rsqrtf(deg);
    }
    __syncthreads();

    // ---- phase 6: w_src[i] = c_i * sum_{j in row_i} c_j ----
    if (t < MM) {
        unsigned long long m = s_row[t];
        float sum = 0.0f;
        while (m) {
            int j = __ffsll((long long)m) - 1;
            sum += s_c[j];
            m &= (m - 1);
        }
        s_w[t] = s_c[t] * sum;
    }

    cp_async_wait<0>();               // features landed
    __syncthreads();

    // ---- phase 7: mix = sum_i w_i * feat_tile[i]  (quad-partitioned, smem) ----
    {
        const int q = t >> 6;        // 0..3
        const int j = t & 63;        // float4 index within row
        float4 acc = make_float4(0.f, 0.f, 0.f, 0.f);
        for (int i = q; i < MM; i += 4) {
            float  wv = s_w[i];
            float4 f4 = s_feat[i][j];
            acc.x = fmaf(wv, f4.x, acc.x);
            acc.y = fmaf(wv, f4.y, acc.y);
            acc.z = fmaf(wv, f4.z, acc.z);
            acc.w = fmaf(wv, f4.w, acc.w);
        }
        s_acc[q][j] = acc;
    }
    __syncthreads();

    if (t < 64) {
        float4 a0 = s_acc[0][t], a1 = s_acc[1][t];
        float4 a2 = s_acc[2][t], a3 = s_acc[3][t];
        float4 r;
        r.x = (a0.x + a1.x) + (a2.x + a3.x);
        r.y = (a0.y + a1.y) + (a2.y + a3.y);
        r.z = (a0.z + a1.z) + (a2.z + a3.z);
        r.w = (a0.w + a1.w) + (a2.w + a3.w);
        *reinterpret_cast<float4*>(&g_mix[(size_t)b * NF + t * 4]) = r;
        if (t == 0) g_c0[b] = s_c[0];
    }
}

// ---------------------------------------------------------------------------
// Kernel B: out = relu(mix @ W + c0 * feat[batch_nodes])
// 64x64 tile, BK=16, 256 threads, 4x4 microtile, register double-buffer.
// grid = (4, 157) = 628 CTAs -> ~4 CTAs/SM.
// ---------------------------------------------------------------------------
#define BM 64
#define BN 64
#define BK 16

__global__ void __launch_bounds__(256) gemm_kernel(
    const float* __restrict__ W,      // [NF, NF] row-major (k, n)
    const float* __restrict__ feat,   // [N_NODES, NF]
    const int*   __restrict__ bn,     // [B]
    float*       __restrict__ out,    // [B, NF]
    int B)
{
    __shared__ __align__(16) float sA[BK][BM];   // transposed A tile
    __shared__ __align__(16) float sB[BK][BN];

    const int tid = threadIdx.x;
    const int bm0 = blockIdx.y * BM;
    const int bn0 = blockIdx.x * BN;
    const int ty  = tid >> 4;         // 0..15 -> rows ty*4 .. +3
    const int tx  = tid & 15;         // 0..15 -> cols tx*4 .. +3

    const int arow = tid >> 2;        // 0..63
    const int acol = (tid & 3) * 4;   // 0,4,8,12
    const int brow = tid >> 4;        // 0..15
    const int bcol = (tid & 15) * 4;  // 0..60

    const int agr   = bm0 + arow;
    const bool aok  = (agr < B);
    const float* aP = &g_mix[(size_t)agr * NF + acol];
    const float* bP = &W[(size_t)brow * NF + bn0 + bcol];

    float acc[4][4];
    #pragma unroll
    for (int m = 0; m < 4; m++)
        #pragma unroll
        for (int n = 0; n < 4; n++) acc[m][n] = 0.0f;

    // prefetch first K-tile into registers
    float4 nA = aok ? *reinterpret_cast<const float4*>(aP)
                    : make_float4(0.f, 0.f, 0.f, 0.f);
    float4 nB = *reinterpret_cast<const float4*>(bP);

    for (int kk = 0; kk < NF; kk += BK) {
        // commit current tile to smem
        sA[acol + 0][arow] = nA.x;
        sA[acol + 1][arow] = nA.y;
        sA[acol + 2][arow] = nA.z;
        sA[acol + 3][arow] = nA.w;
        *reinterpret_cast<float4*>(&sB[brow][bcol]) = nB;
        __syncthreads();

        // prefetch next tile (LDG latency overlaps the compute below)
        if (kk + BK < NF) {
            nA = aok ? *reinterpret_cast<const float4*>(aP + kk + BK)
                     : make_float4(0.f, 0.f, 0.f, 0.f);
            nB = *reinterpret_cast<const float4*>(bP + (size_t)(kk + BK) * NF);
        }

        #pragma unroll
        for (int k = 0; k < BK; k++) {
            float4 ra = *reinterpret_cast<const float4*>(&sA[k][ty * 4]);
            float4 rb = *reinterpret_cast<const float4*>(&sB[k][tx * 4]);
            float am[4] = {ra.x, ra.y, ra.z, ra.w};
            float bnv[4] = {rb.x, rb.y, rb.z, rb.w};
            #pragma unroll
            for (int m = 0; m < 4; m++)
                #pragma unroll
                for (int n = 0; n < 4; n++)
                    acc[m][n] = fmaf(am[m], bnv[n], acc[m][n]);
        }
        __syncthreads();
    }

    // epilogue: relu(acc + c0[row] * feat[bn[row]][col]), float4 stores
    #pragma unroll
    for (int m = 0; m < 4; m++) {
        int gr = bm0 + ty * 4 + m;
        if (gr >= B) continue;
        int   node = bn[gr];
        float cc   = g_c0[gr];
        int   gc   = bn0 + tx * 4;
        float4 h4 = *reinterpret_cast<const float4*>(
                        &feat[(size_t)node * NF + gc]);
        float4 r;
        r.x = fmaxf(acc[m][0] + cc * h4.x, 0.0f);
        r.y = fmaxf(acc[m][1] + cc * h4.y, 0.0f);
        r.z = fmaxf(acc[m][2] + cc * h4.z, 0.0f);
        r.w = fmaxf(acc[m][3] + cc * h4.w, 0.0f);
        *reinterpret_cast<float4*>(&out[(size_t)gr * NF + gc]) = r;
    }
}

// ---------------------------------------------------------------------------
extern "C" void kernel_launch(void* const* d_in, const int* in_sizes, int n_in,
                              void* d_out, int out_size)
{
    const float* feat = (const float*)d_in[0];   // node_features [50000,256]
    const float* W    = (const float*)d_in[1];   // weight [256,256]
    const int*   adj  = (const int*)d_in[2];     // adj [50000,32]
    const int*   bn   = (const int*)d_in[3];     // batch_nodes [B]
    float*       out  = (float*)d_out;

    const int B = in_sizes[3];

    subgraph_kernel<<<B, 256>>>(feat, adj, bn, B);

    dim3 grid(NF / BN, (B + BM - 1) / BM);
    gemm_kernel<<<grid, 256>>>(W, feat, bn, out, B);
}